// round 12
// baseline (speedup 1.0000x reference)
#include <cuda_runtime.h>
#include <cuda_bf16.h>
#include <math.h>
#include <stdint.h>

// Model dims
#define SEQ   1024
#define DM    768
#define DI    1536
#define DS    16
#define DTR   48
#define VOCAB 50280
#define NLAYER 24

// ---------------- scratch buffers (device globals; no allocation) ------------
__device__ float g_xp  [6 * SEQ * DM];        // out_proj split-K partials
__device__ float g_xzp [3 * SEQ * 2 * DI];    // in_proj split-K partials
__device__ float g_res [SEQ * DM];
__device__ float g_lres[SEQ * DM];
__device__ float g_xz  [SEQ * 2 * DI];
__device__ float g_xs  [SEQ * DI];
__device__ float g_dbc [SEQ * 80];
__device__ float g_dt  [SEQ * DI];

// bf16 3-term activation triples
__device__ __nv_bfloat16 g_a3[SEQ * 3 * DI];

// bf16 3-term weights (one-time)
__device__ __nv_bfloat16 g_win [(size_t)NLAYER * 3072 * 2304];
__device__ __nv_bfloat16 g_wout[(size_t)NLAYER * 768 * 4608];
__device__ __nv_bfloat16 g_lmbf[(size_t)VOCAB * 2304];

__device__ __forceinline__ uint32_t smem_u32(const void* p) {
    uint32_t a;
    asm("{ .reg .u64 t; cvta.to.shared.u64 t, %1; cvt.u32.u64 %0, t; }"
        : "=r"(a) : "l"(p));
    return a;
}
__device__ __forceinline__ void cp16(uint32_t dst, const void* src) {
    asm volatile("cp.async.cg.shared.global [%0], [%1], 16;"
                 :: "r"(dst), "l"(src));
}
__device__ __forceinline__ void cp_commit() {
    asm volatile("cp.async.commit_group;" ::: "memory");
}
__device__ __forceinline__ void cp_wait1() {
    asm volatile("cp.async.wait_group 1;" ::: "memory");
}

// ============ warp-MMA bf16 GEMM: C[M,N] = A[M,K] * B[N,K]^T =================
// 128x128x64 CTA stage, 16 warps in 4x4 grid, warp tile 32x32 (min LDSM traffic:
// 2 A + 2 B ldmatrix per kst per warp), cp.async 3-stage pipe, 2 CTAs/SM.
// blockIdx.z selects a K slice (koff = z*Kp) and output slice (C + z*cslice).
#define RSTR 144
#define STAGE_BYTES (2 * 128 * RSTR)       // 36864
#define GEMM_SMEM   (3 * STAGE_BYTES)      // 110592

__global__ void __launch_bounds__(512, 2) gemm_bf16(
    const __nv_bfloat16* __restrict__ A, const __nv_bfloat16* __restrict__ B,
    float* __restrict__ C, int Ntot, int Kp, int lda, int ldb, int ldc, int cslice)
{
    extern __shared__ __align__(16) char smem[];
    uint32_t smemU = smem_u32(smem);

    int tid = threadIdx.x;
    int lane = tid & 31, wid = tid >> 5;
    int warp_m = wid >> 2, warp_n = wid & 3;   // 4 x 4 warp grid
    int bm = blockIdx.y << 7, bn = blockIdx.x << 7;
    int nstage = Kp >> 6;
    size_t koff = (size_t)blockIdx.z * Kp * 2;
    float* Cw = C + (size_t)blockIdx.z * cslice;

    int crow = tid >> 2;
    int ccol = (tid & 3) * 32;
    size_t ldaB = (size_t)lda * 2, ldbB = (size_t)ldb * 2;
    const char* Asrc = (const char*)A + (size_t)(bm + crow) * ldaB + koff + ccol;
    int brow = bn + crow; if (brow >= Ntot) brow = Ntot - 1;
    const char* Bsrc = (const char*)B + (size_t)brow * ldbB + koff + ccol;
    uint32_t dA = smemU + crow * RSTR + ccol;
    uint32_t dB = dA + 128 * RSTR;

    // ldmatrix per-lane relative addresses
    int lrow = lane & 7, g = lane >> 3;
    uint32_t aRel[2], bRel[2];
#pragma unroll
    for (int mt = 0; mt < 2; mt++) {
        int row = warp_m * 32 + mt * 16 + (g & 1) * 8 + lrow;
        int col = (g >> 1) * 8;
        aRel[mt] = smemU + row * RSTR + col * 2;
    }
#pragma unroll
    for (int j = 0; j < 2; j++) {
        int row = warp_n * 32 + j * 16 + (g >> 1) * 8 + lrow;
        int col = (g & 1) * 8;
        bRel[j] = smemU + 128 * RSTR + row * RSTR + col * 2;
    }

    float acc[2][4][4];
#pragma unroll
    for (int mt = 0; mt < 2; mt++)
#pragma unroll
        for (int nt = 0; nt < 4; nt++)
#pragma unroll
            for (int e = 0; e < 4; e++) acc[mt][nt][e] = 0.f;

#pragma unroll
    for (int s = 0; s < 2; s++) {
        size_t ko = (size_t)s * 128;
        uint32_t sb = s * STAGE_BYTES;
        cp16(dA + sb,      Asrc + ko);
        cp16(dA + sb + 16, Asrc + ko + 16);
        cp16(dB + sb,      Bsrc + ko);
        cp16(dB + sb + 16, Bsrc + ko + 16);
        cp_commit();
    }

    int s = 0;
    for (int ks = 0; ks < nstage; ks++) {
        cp_wait1();
        __syncthreads();

        if (ks + 2 < nstage) {
            int sn = s + 2; if (sn >= 3) sn -= 3;
            size_t ko = (size_t)(ks + 2) * 128;
            uint32_t sb = sn * STAGE_BYTES;
            cp16(dA + sb,      Asrc + ko);
            cp16(dA + sb + 16, Asrc + ko + 16);
            cp16(dB + sb,      Bsrc + ko);
            cp16(dB + sb + 16, Bsrc + ko + 16);
        }
        cp_commit();

        uint32_t sb = s * STAGE_BYTES;
#pragma unroll
        for (int kst = 0; kst < 4; kst++) {
            uint32_t ko = sb + kst * 32;
            uint32_t af[2][4];
#pragma unroll
            for (int mt = 0; mt < 2; mt++)
                asm volatile(
                    "ldmatrix.sync.aligned.m8n8.x4.shared.b16 {%0,%1,%2,%3}, [%4];"
                    : "=r"(af[mt][0]), "=r"(af[mt][1]),
                      "=r"(af[mt][2]), "=r"(af[mt][3])
                    : "r"(aRel[mt] + ko));
            uint32_t bf[4][2];
#pragma unroll
            for (int j = 0; j < 2; j++)
                asm volatile(
                    "ldmatrix.sync.aligned.m8n8.x4.shared.b16 {%0,%1,%2,%3}, [%4];"
                    : "=r"(bf[2 * j][0]), "=r"(bf[2 * j][1]),
                      "=r"(bf[2 * j + 1][0]), "=r"(bf[2 * j + 1][1])
                    : "r"(bRel[j] + ko));
#pragma unroll
            for (int mt = 0; mt < 2; mt++)
#pragma unroll
                for (int nt = 0; nt < 4; nt++) {
                    asm volatile(
                        "mma.sync.aligned.m16n8k16.row.col.f32.bf16.bf16.f32 "
                        "{%0,%1,%2,%3}, {%4,%5,%6,%7}, {%8,%9}, {%0,%1,%2,%3};"
                        : "+f"(acc[mt][nt][0]), "+f"(acc[mt][nt][1]),
                          "+f"(acc[mt][nt][2]), "+f"(acc[mt][nt][3])
                        : "r"(af[mt][0]), "r"(af[mt][1]),
                          "r"(af[mt][2]), "r"(af[mt][3]),
                          "r"(bf[nt][0]), "r"(bf[nt][1]));
                }
        }
        if (++s >= 3) s -= 3;
    }

#pragma unroll
    for (int mt = 0; mt < 2; mt++) {
        int m0 = bm + warp_m * 32 + mt * 16 + (lane >> 2);
#pragma unroll
        for (int nt = 0; nt < 4; nt++) {
            int n0 = bn + warp_n * 32 + nt * 8 + (lane & 3) * 2;
            if (n0 < Ntot) {
                *(float2*)&Cw[(size_t)m0 * ldc + n0] =
                    make_float2(acc[mt][nt][0], acc[mt][nt][1]);
                *(float2*)&Cw[(size_t)(m0 + 8) * ldc + n0] =
                    make_float2(acc[mt][nt][2], acc[mt][nt][3]);
            }
        }
    }
}

// ------------- fp32 -> bf16 3-term split (weights, [hi|hi|lo]) ----------------
__global__ void k_cvt3(const float* __restrict__ src, __nv_bfloat16* __restrict__ dst,
                       int K, int total)
{
    int i = blockIdx.x * blockDim.x + threadIdx.x;
    if (i >= total) return;
    int r = i / K, k = i - r * K;
    float x = src[i];
    __nv_bfloat16 hi = __float2bfloat16(x);
    __nv_bfloat16 lo = __float2bfloat16(x - __bfloat162float(hi));
    size_t base = (size_t)r * 3 * K + k;
    dst[base]                 = hi;
    dst[base + K]             = hi;
    dst[base + 2 * (size_t)K] = lo;
}

// ---------------- init: embedding gather + zero residual/partials -------------
__global__ void k_init(const int* __restrict__ ids, const float* __restrict__ emb)
{
    int i = blockIdx.x * blockDim.x + threadIdx.x;
    if (i < SEQ * DM) {
        int t = i / DM, c = i - t * DM;
        g_xp[i] = emb[(size_t)ids[t] * DM + c];
#pragma unroll
        for (int z = 1; z < 6; z++) g_xp[i + z * SEQ * DM] = 0.f;
        g_res[i] = 0.f;
    }
}

// ---------------- sum in_proj split-K partials -> g_xz ------------------------
__global__ void k_sumxz()
{
    int i = blockIdx.x * blockDim.x + threadIdx.x;
    if (i < SEQ * 2 * DI)
        g_xz[i] = g_xzp[i] + g_xzp[i + SEQ * 2 * DI] + g_xzp[i + 2 * SEQ * 2 * DI];
}

// ------- fused (lres ops) + residual add + RMSNorm + A-triple [hi|lo|hi] ------
#define F_ADD  1
#define F_SAVE 2
__global__ void __launch_bounds__(256) k_addnorm(const float* __restrict__ w, int flags)
{
    int r = blockIdx.x;
    int tid = threadIdx.x;
    float v[3];
    float ss = 0.f;
#pragma unroll
    for (int j = 0; j < 3; j++) {
        int c = tid + j * 256;
        int i = r * DM + c;
        float res = g_res[i];
        if (flags & F_ADD)  res += g_lres[i];
        if (flags & F_SAVE) g_lres[i] = res;
        float t = res;
#pragma unroll
        for (int z = 0; z < 6; z++) t += g_xp[i + z * SEQ * DM];
        g_res[i] = t;
        v[j] = t;
        ss += t * t;
    }
#pragma unroll
    for (int o = 16; o; o >>= 1) ss += __shfl_xor_sync(0xffffffffu, ss, o);
    __shared__ float red[8];
    __shared__ float scale;
    if ((tid & 31) == 0) red[tid >> 5] = ss;
    __syncthreads();
    if (tid == 0) {
        float s = 0.f;
#pragma unroll
        for (int i = 0; i < 8; i++) s += red[i];
        scale = rsqrtf(s * (1.0f / DM) + 1e-5f);
    }
    __syncthreads();
    float sc = scale;
#pragma unroll
    for (int j = 0; j < 3; j++) {
        int c = tid + j * 256;
        float x = v[j] * sc * w[c];
        __nv_bfloat16 hi = __float2bfloat16(x);
        __nv_bfloat16 lo = __float2bfloat16(x - __bfloat162float(hi));
        size_t base = (size_t)r * 2304 + c;
        g_a3[base]        = hi;
        g_a3[base + 768]  = lo;
        g_a3[base + 1536] = hi;
    }
}

// ------ fused depthwise conv + SiLU + x_proj + dt_proj (8 rows per CTA) -------
// dyn smem: xs[8][DI] floats (48KB) + dbc[8][80] floats (2.5KB)
#define CONVX_SMEM (8 * DI * 4 + 8 * 80 * 4)
__global__ void __launch_bounds__(256) k_convx(const float* __restrict__ cw,
                                               const float* __restrict__ cb,
                                               const float* __restrict__ Bw,
                                               const float* __restrict__ dtw,
                                               const float* __restrict__ dtb)
{
    extern __shared__ float cxs[];
    float (*xs)[DI] = (float (*)[DI])cxs;
    float (*sdbc)[80] = (float (*)[80])(cxs + 8 * DI);

    int t0 = blockIdx.x * 8;
    int tid = threadIdx.x;
    for (int i = tid; i < 8 * DI; i += 256) {
        int r = i / DI, d = i - r * DI;
        int t = t0 + r;
        float s = cb[d];
        const float* w = cw + d * 4;
#pragma unroll
        for (int j = 0; j < 4; j++) {
            int tt = t - 3 + j;
            if (tt >= 0) s = fmaf(w[j], g_xz[tt * 2 * DI + d], s);
        }
        float v = s / (1.f + __expf(-s));
        xs[r][d] = v;
        g_xs[(size_t)t * DI + d] = v;
    }
    __syncthreads();

    // x_proj: 80 outputs per row
    int w = tid >> 5, lane = tid & 31;
    for (int n = w; n < 80; n += 8) {
        const float* bp = Bw + (size_t)n * DI;
        float acc[8];
#pragma unroll
        for (int r = 0; r < 8; r++) acc[r] = 0.f;
        for (int k = lane; k < DI; k += 32) {
            float wv = bp[k];
#pragma unroll
            for (int r = 0; r < 8; r++) acc[r] = fmaf(xs[r][k], wv, acc[r]);
        }
#pragma unroll
        for (int r = 0; r < 8; r++) {
#pragma unroll
            for (int o = 16; o; o >>= 1)
                acc[r] += __shfl_xor_sync(0xffffffffu, acc[r], o);
        }
        if (lane < 8) {
            sdbc[lane][n] = acc[lane];
            if (n >= 48) g_dbc[(size_t)(t0 + lane) * 80 + n] = acc[lane];
        }
    }
    __syncthreads();

    // dt_proj: dt[r][d] = softplus(sum_k sdbc[r][k] * dtw[d][k] + dtb[d])
    for (int d = tid; d < DI; d += 256) {
        const float* wrow = dtw + (size_t)d * DTR;
        float b = dtb[d];
        float acc[8];
#pragma unroll
        for (int r = 0; r < 8; r++) acc[r] = b;
        for (int k = 0; k < DTR; k++) {
            float wv = wrow[k];
#pragma unroll
            for (int r = 0; r < 8; r++) acc[r] = fmaf(sdbc[r][k], wv, acc[r]);
        }
#pragma unroll
        for (int r = 0; r < 8; r++) {
            float vv = acc[r];
            vv = (vv > 15.f) ? vv : log1pf(__expf(vv));
            g_dt[(size_t)(t0 + r) * DI + d] = vv;
        }
    }
}

// ---- selective scan: phase-structured (exp batch / recurrence / shfl batch) --
#define SU 8
__global__ void __launch_bounds__(256) k_scan(const float* __restrict__ Alog,
                                              const float* __restrict__ Dp)
{
    int tid = threadIdx.x;
    int grp = tid >> 4;
    int n = tid & 15;
    int d = blockIdx.x * 16 + grp;

    float A  = -__expf(Alog[d * DS + n]);
    float Dd = Dp[d];
    float h = 0.f;

    const float* dtp = g_dt + d;
    const float* xsp = g_xs + d;
    const float* zp  = g_xz + DI + d;
    const float* bp  = g_dbc + 48 + n;
    const float* cp  = g_dbc + 64 + n;

    float pd[SU], px[SU], pb[SU], pc[SU], pz[SU];
#pragma unroll
    for (int i = 0; i < SU; i++) {
        pd[i] = dtp[i * DI];
        px[i] = xsp[i * DI];
        pb[i] = bp[i * 80];
        pc[i] = cp[i * 80];
        pz[i] = zp[i * 2 * DI];
    }

    for (int t0 = 0; t0 < SEQ; t0 += SU) {
        float cd[SU], cx[SU], cb[SU], cc[SU], cz[SU];
#pragma unroll
        for (int i = 0; i < SU; i++) {
            cd[i] = pd[i]; cx[i] = px[i]; cb[i] = pb[i];
            cc[i] = pc[i]; cz[i] = pz[i];
        }
        int tn = t0 + SU;
        if (tn < SEQ) {
#pragma unroll
            for (int i = 0; i < SU; i++) {
                pd[i] = dtp[(tn + i) * DI];
                px[i] = xsp[(tn + i) * DI];
                pb[i] = bp[(tn + i) * 80];
                pc[i] = cp[(tn + i) * 80];
                pz[i] = zp[(tn + i) * 2 * DI];
            }
        }
        float ex[SU], db[SU];
#pragma unroll
        for (int i = 0; i < SU; i++) {
            ex[i] = __expf(cd[i] * A);
            db[i] = cd[i] * cb[i] * cx[i];
        }
        float hv[SU];
#pragma unroll
        for (int i = 0; i < SU; i++) {
            h = fmaf(ex[i], h, db[i]);
            hv[i] = h;
        }
        float yp[SU];
#pragma unroll
        for (int i = 0; i < SU; i++) yp[i] = hv[i] * cc[i];
#pragma unroll
        for (int o = 8; o; o >>= 1) {
#pragma unroll
            for (int i = 0; i < SU; i++)
                yp[i] += __shfl_xor_sync(0xffffffffu, yp[i], o);
        }
        if (n == 0) {
#pragma unroll
            for (int i = 0; i < SU; i++) {
                float z = cz[i];
                float y = fmaf(Dd, cx[i], yp[i]);
                float gv = y * (z / (1.f + __expf(-z)));
                __nv_bfloat16 hi = __float2bfloat16(gv);
                __nv_bfloat16 lo = __float2bfloat16(gv - __bfloat162float(hi));
                size_t base = (size_t)(t0 + i) * 4608 + d;
                g_a3[base]        = hi;
                g_a3[base + 1536] = lo;
                g_a3[base + 3072] = hi;
            }
        }
    }
}

// ---------------- host orchestration ------------------------------------------
extern "C" void kernel_launch(void* const* d_in, const int* in_sizes, int n_in,
                              void* d_out, int out_size)
{
    (void)in_sizes; (void)n_in; (void)out_size;
    const int*   ids   = (const int*)  d_in[0];
    const float* emb   = (const float*)d_in[1];
    const float* inw   = (const float*)d_in[2];
    const float* convw = (const float*)d_in[3];
    const float* convb = (const float*)d_in[4];
    const float* xpw   = (const float*)d_in[5];
    const float* dtw   = (const float*)d_in[6];
    const float* dtb   = (const float*)d_in[7];
    const float* alog  = (const float*)d_in[8];
    const float* Dp    = (const float*)d_in[9];
    const float* outw  = (const float*)d_in[10];
    const float* nw    = (const float*)d_in[11];
    const float* nfw   = (const float*)d_in[12];
    const float* lmw   = (const float*)d_in[13];
    float* out = (float*)d_out;

    static float *p_xzp = nullptr, *p_xp = nullptr;
    static __nv_bfloat16 *p_a3 = nullptr, *p_win = nullptr, *p_wout = nullptr,
                         *p_lmbf = nullptr;
    if (!p_xzp) {
        cudaGetSymbolAddress((void**)&p_xzp,  g_xzp);
        cudaGetSymbolAddress((void**)&p_xp,   g_xp);
        cudaGetSymbolAddress((void**)&p_a3,   g_a3);
        cudaGetSymbolAddress((void**)&p_win,  g_win);
        cudaGetSymbolAddress((void**)&p_wout, g_wout);
        cudaGetSymbolAddress((void**)&p_lmbf, g_lmbf);
        cudaFuncSetAttribute(gemm_bf16,
                             cudaFuncAttributeMaxDynamicSharedMemorySize,
                             GEMM_SMEM);
        cudaFuncSetAttribute(k_convx,
                             cudaFuncAttributeMaxDynamicSharedMemorySize,
                             CONVX_SMEM);
    }

    const int EW = (SEQ * DM) / 256;

    // Launch order: index 3 = in_proj GEMM (ncu capture slot).
    k_init<<<EW, 256>>>(ids, emb);                               // 0
    {
        int tin = NLAYER * 3072 * DM;
        k_cvt3<<<(tin + 255) / 256, 256>>>(inw, p_win, DM, tin); // 1
    }

    for (int step = 0; step < 28; step++) {
        int li = (step < 22) ? step : 22 + ((step - 22) & 1);
        int flags = 0;
        if (step == 22) flags = F_SAVE;
        else if (step == 24 || step == 26) flags = F_ADD | F_SAVE;

        k_addnorm<<<SEQ, 256>>>(nw + (size_t)li * DM, flags);    // 2 (step 0)

        // in_proj split-K=3: g_xzp[z] = a3[:,z] @ win[:,z]^T  (1024 x 3072)
        gemm_bf16<<<dim3(24, 8, 3), 512, GEMM_SMEM>>>(           // 3 <- profiled
            p_a3, p_win + (size_t)li * 3072 * 2304, p_xzp,
            3072, 768, 2304, 2304, 3072, SEQ * 2 * DI);

        // sum partials -> g_xz
        k_sumxz<<<(SEQ * 2 * DI) / 256, 256>>>();

        // fused conv + silu + x_proj + dt_proj
        k_convx<<<SEQ / 8, 256, CONVX_SMEM>>>(
            convw + (size_t)li * DI * 4, convb + (size_t)li * DI,
            xpw + (size_t)li * 80 * DI,
            dtw + (size_t)li * DI * DTR, dtb + (size_t)li * DI);

        // selective scan + gate -> A-triple g_a3 (1024 x 4608)
        k_scan<<<DI / 16, 256>>>(alog + (size_t)li * DI * DS,
                                 Dp + (size_t)li * DI);

        if (step == 0) {
            int tout = NLAYER * DM * DI;
            k_cvt3<<<(tout + 255) / 256, 256>>>(outw, p_wout, DI, tout);
        }

        // out_proj split-K=6: g_xp[z] = a3[:,z] @ wout[:,z]^T  (1024 x 768)
        gemm_bf16<<<dim3(6, 8, 6), 512, GEMM_SMEM>>>(
            p_a3, p_wout + (size_t)li * DM * 4608, p_xp,
            DM, 768, 4608, 4608, DM, SEQ * DM);
    }

    k_addnorm<<<SEQ, 256>>>(nfw, F_ADD);

    {
        int tlm = VOCAB * DM;
        k_cvt3<<<(tlm + 255) / 256, 256>>>(lmw, p_lmbf, DM, tlm);
    }
    // lm_head: out = a3 @ lmbf^T  (1024 x 50280, K'=2304)
    gemm_bf16<<<dim3((VOCAB + 127) / 128, 8, 1), 512, GEMM_SMEM>>>(
        p_a3, p_lmbf, out, VOCAB, 2304, 2304, 2304, VOCAB, 0);
}

// round 13
// speedup vs baseline: 1.0722x; 1.0722x over previous
#include <cuda_runtime.h>
#include <cuda_bf16.h>
#include <math.h>
#include <stdint.h>

// Model dims
#define SEQ   1024
#define DM    768
#define DI    1536
#define DS    16
#define DTR   48
#define VOCAB 50280
#define NLAYER 24

// ---------------- scratch buffers (device globals; no allocation) ------------
__device__ float g_xp  [6 * SEQ * DM];        // out_proj split-K partials
__device__ float g_xzp [3 * SEQ * 2 * DI];    // in_proj split-K partials
__device__ float g_res [SEQ * DM];
__device__ float g_lres[SEQ * DM];
__device__ float g_xz  [SEQ * 2 * DI];
__device__ float g_xs  [SEQ * DI];
__device__ float g_dbc [SEQ * 80];
__device__ float g_dt  [SEQ * DI];

// bf16 3-term activation triples
__device__ __nv_bfloat16 g_a3[SEQ * 3 * DI];

// bf16 3-term weights (one-time)
__device__ __nv_bfloat16 g_win [(size_t)NLAYER * 3072 * 2304];
__device__ __nv_bfloat16 g_wout[(size_t)NLAYER * 768 * 4608];
__device__ __nv_bfloat16 g_lmbf[(size_t)VOCAB * 2304];

__device__ __forceinline__ uint32_t smem_u32(const void* p) {
    uint32_t a;
    asm("{ .reg .u64 t; cvta.to.shared.u64 t, %1; cvt.u32.u64 %0, t; }"
        : "=r"(a) : "l"(p));
    return a;
}
__device__ __forceinline__ void cp16(uint32_t dst, const void* src) {
    asm volatile("cp.async.cg.shared.global [%0], [%1], 16;"
                 :: "r"(dst), "l"(src));
}
__device__ __forceinline__ void cp_commit() {
    asm volatile("cp.async.commit_group;" ::: "memory");
}
__device__ __forceinline__ void cp_wait1() {
    asm volatile("cp.async.wait_group 1;" ::: "memory");
}

// ============ warp-MMA bf16 GEMM: C[M,N] = A[M,K] * B[N,K]^T =================
// 128x128x64 CTA stage, 16 warps in 4x4 grid, warp tile 32x32 (min LDSM traffic),
// cp.async 3-stage pipe, 512 threads, <=64 regs -> 2 CTAs/SM.
// blockIdx.z selects a K slice (koff = z*Kp) and output slice (C + z*cslice).
#define RSTR 144
#define STAGE_BYTES (2 * 128 * RSTR)       // 36864
#define GEMM_SMEM   (3 * STAGE_BYTES)      // 110592

__global__ void __launch_bounds__(512, 2) gemm_bf16(
    const __nv_bfloat16* __restrict__ A, const __nv_bfloat16* __restrict__ B,
    float* __restrict__ C, int Ntot, int Kp, int lda, int ldb, int ldc, int cslice)
{
    extern __shared__ __align__(16) char smem[];
    uint32_t smemU = smem_u32(smem);

    int tid = threadIdx.x;
    int lane = tid & 31, wid = tid >> 5;
    int warp_m = wid >> 2, warp_n = wid & 3;   // 4 x 4 warp grid
    int bm = blockIdx.y << 7, bn = blockIdx.x << 7;
    int nstage = Kp >> 6;
    size_t koff = (size_t)blockIdx.z * Kp * 2;
    float* Cw = C + (size_t)blockIdx.z * cslice;

    int crow = tid >> 2;
    int ccol = (tid & 3) * 32;
    size_t ldaB = (size_t)lda * 2, ldbB = (size_t)ldb * 2;
    const char* Asrc = (const char*)A + (size_t)(bm + crow) * ldaB + koff + ccol;
    int brow = bn + crow; if (brow >= Ntot) brow = Ntot - 1;
    const char* Bsrc = (const char*)B + (size_t)brow * ldbB + koff + ccol;
    uint32_t dA = smemU + crow * RSTR + ccol;
    uint32_t dB = dA + 128 * RSTR;

    int lrow = lane & 7, g = lane >> 3;
    uint32_t aRel[2], bRel[2];
#pragma unroll
    for (int mt = 0; mt < 2; mt++) {
        int row = warp_m * 32 + mt * 16 + (g & 1) * 8 + lrow;
        int col = (g >> 1) * 8;
        aRel[mt] = smemU + row * RSTR + col * 2;
    }
#pragma unroll
    for (int j = 0; j < 2; j++) {
        int row = warp_n * 32 + j * 16 + (g >> 1) * 8 + lrow;
        int col = (g & 1) * 8;
        bRel[j] = smemU + 128 * RSTR + row * RSTR + col * 2;
    }

    float acc[2][4][4];
#pragma unroll
    for (int mt = 0; mt < 2; mt++)
#pragma unroll
        for (int nt = 0; nt < 4; nt++)
#pragma unroll
            for (int e = 0; e < 4; e++) acc[mt][nt][e] = 0.f;

#pragma unroll
    for (int s = 0; s < 2; s++) {
        size_t ko = (size_t)s * 128;
        uint32_t sb = s * STAGE_BYTES;
        cp16(dA + sb,      Asrc + ko);
        cp16(dA + sb + 16, Asrc + ko + 16);
        cp16(dB + sb,      Bsrc + ko);
        cp16(dB + sb + 16, Bsrc + ko + 16);
        cp_commit();
    }

    int s = 0;
    for (int ks = 0; ks < nstage; ks++) {
        cp_wait1();
        __syncthreads();

        if (ks + 2 < nstage) {
            int sn = s + 2; if (sn >= 3) sn -= 3;
            size_t ko = (size_t)(ks + 2) * 128;
            uint32_t sb = sn * STAGE_BYTES;
            cp16(dA + sb,      Asrc + ko);
            cp16(dA + sb + 16, Asrc + ko + 16);
            cp16(dB + sb,      Bsrc + ko);
            cp16(dB + sb + 16, Bsrc + ko + 16);
        }
        cp_commit();

        uint32_t sb = s * STAGE_BYTES;
#pragma unroll
        for (int kst = 0; kst < 4; kst++) {
            uint32_t ko = sb + kst * 32;
            uint32_t af[2][4];
#pragma unroll
            for (int mt = 0; mt < 2; mt++)
                asm volatile(
                    "ldmatrix.sync.aligned.m8n8.x4.shared.b16 {%0,%1,%2,%3}, [%4];"
                    : "=r"(af[mt][0]), "=r"(af[mt][1]),
                      "=r"(af[mt][2]), "=r"(af[mt][3])
                    : "r"(aRel[mt] + ko));
            uint32_t bf[4][2];
#pragma unroll
            for (int j = 0; j < 2; j++)
                asm volatile(
                    "ldmatrix.sync.aligned.m8n8.x4.shared.b16 {%0,%1,%2,%3}, [%4];"
                    : "=r"(bf[2 * j][0]), "=r"(bf[2 * j][1]),
                      "=r"(bf[2 * j + 1][0]), "=r"(bf[2 * j + 1][1])
                    : "r"(bRel[j] + ko));
#pragma unroll
            for (int mt = 0; mt < 2; mt++)
#pragma unroll
                for (int nt = 0; nt < 4; nt++) {
                    asm volatile(
                        "mma.sync.aligned.m16n8k16.row.col.f32.bf16.bf16.f32 "
                        "{%0,%1,%2,%3}, {%4,%5,%6,%7}, {%8,%9}, {%0,%1,%2,%3};"
                        : "+f"(acc[mt][nt][0]), "+f"(acc[mt][nt][1]),
                          "+f"(acc[mt][nt][2]), "+f"(acc[mt][nt][3])
                        : "r"(af[mt][0]), "r"(af[mt][1]),
                          "r"(af[mt][2]), "r"(af[mt][3]),
                          "r"(bf[nt][0]), "r"(bf[nt][1]));
                }
        }
        if (++s >= 3) s -= 3;
    }

#pragma unroll
    for (int mt = 0; mt < 2; mt++) {
        int m0 = bm + warp_m * 32 + mt * 16 + (lane >> 2);
#pragma unroll
        for (int nt = 0; nt < 4; nt++) {
            int n0 = bn + warp_n * 32 + nt * 8 + (lane & 3) * 2;
            if (n0 < Ntot) {
                *(float2*)&Cw[(size_t)m0 * ldc + n0] =
                    make_float2(acc[mt][nt][0], acc[mt][nt][1]);
                *(float2*)&Cw[(size_t)(m0 + 8) * ldc + n0] =
                    make_float2(acc[mt][nt][2], acc[mt][nt][3]);
            }
        }
    }
}

// ------------- fp32 -> bf16 3-term split (weights, [hi|hi|lo]) ----------------
__global__ void k_cvt3(const float* __restrict__ src, __nv_bfloat16* __restrict__ dst,
                       int K, int total)
{
    int i = blockIdx.x * blockDim.x + threadIdx.x;
    if (i >= total) return;
    int r = i / K, k = i - r * K;
    float x = src[i];
    __nv_bfloat16 hi = __float2bfloat16(x);
    __nv_bfloat16 lo = __float2bfloat16(x - __bfloat162float(hi));
    size_t base = (size_t)r * 3 * K + k;
    dst[base]                 = hi;
    dst[base + K]             = hi;
    dst[base + 2 * (size_t)K] = lo;
}

// ---------------- init: embedding gather + zero residual/partials -------------
__global__ void k_init(const int* __restrict__ ids, const float* __restrict__ emb)
{
    int i = blockIdx.x * blockDim.x + threadIdx.x;
    if (i < SEQ * DM) {
        int t = i / DM, c = i - t * DM;
        g_xp[i] = emb[(size_t)ids[t] * DM + c];
#pragma unroll
        for (int z = 1; z < 6; z++) g_xp[i + z * SEQ * DM] = 0.f;
        g_res[i] = 0.f;
    }
}

// ---------------- sum in_proj split-K partials -> g_xz ------------------------
__global__ void k_sumxz()
{
    int i = blockIdx.x * blockDim.x + threadIdx.x;
    if (i < SEQ * 2 * DI)
        g_xz[i] = g_xzp[i] + g_xzp[i + SEQ * 2 * DI] + g_xzp[i + 2 * SEQ * 2 * DI];
}

// ------- fused (lres ops) + residual add + RMSNorm + A-triple [hi|lo|hi] ------
#define F_ADD  1
#define F_SAVE 2
__global__ void __launch_bounds__(256) k_addnorm(const float* __restrict__ w, int flags)
{
    int r = blockIdx.x;
    int tid = threadIdx.x;
    float v[3];
    float ss = 0.f;
#pragma unroll
    for (int j = 0; j < 3; j++) {
        int c = tid + j * 256;
        int i = r * DM + c;
        float res = g_res[i];
        if (flags & F_ADD)  res += g_lres[i];
        if (flags & F_SAVE) g_lres[i] = res;
        float t = res;
#pragma unroll
        for (int z = 0; z < 6; z++) t += g_xp[i + z * SEQ * DM];
        g_res[i] = t;
        v[j] = t;
        ss += t * t;
    }
#pragma unroll
    for (int o = 16; o; o >>= 1) ss += __shfl_xor_sync(0xffffffffu, ss, o);
    __shared__ float red[8];
    __shared__ float scale;
    if ((tid & 31) == 0) red[tid >> 5] = ss;
    __syncthreads();
    if (tid == 0) {
        float s = 0.f;
#pragma unroll
        for (int i = 0; i < 8; i++) s += red[i];
        scale = rsqrtf(s * (1.0f / DM) + 1e-5f);
    }
    __syncthreads();
    float sc = scale;
#pragma unroll
    for (int j = 0; j < 3; j++) {
        int c = tid + j * 256;
        float x = v[j] * sc * w[c];
        __nv_bfloat16 hi = __float2bfloat16(x);
        __nv_bfloat16 lo = __float2bfloat16(x - __bfloat162float(hi));
        size_t base = (size_t)r * 2304 + c;
        g_a3[base]        = hi;
        g_a3[base + 768]  = lo;
        g_a3[base + 1536] = hi;
    }
}

// ---------------- SIMT SGEMM (dt_proj only, K=48) -----------------------------
__global__ void __launch_bounds__(256) sgemm_nt(
    const float* __restrict__ A, const float* __restrict__ B, float* __restrict__ C,
    int N, int K, int lda, int ldb, int ldc,
    const float* __restrict__ bias, int mode)
{
    __shared__ float As[8][132];
    __shared__ float Bs[8][132];
    int tid = threadIdx.x;
    int bm = blockIdx.y << 7;
    int bn = blockIdx.x << 7;
    int lr = tid >> 1;
    int lk = (tid & 1) << 2;
    const float* Ag = A + (size_t)(bm + lr) * lda + lk;
    int brow = bn + lr;
    const float* Bg = B + (size_t)brow * ldb + lk;
    bool bvalid = brow < N;
    int tx = tid & 15, ty = tid >> 4;

    float acc[8][8];
#pragma unroll
    for (int i = 0; i < 8; i++)
#pragma unroll
        for (int j = 0; j < 8; j++) acc[i][j] = 0.f;

    for (int k0 = 0; k0 < K; k0 += 8) {
        float4 av = *(const float4*)(Ag + k0);
        float4 bv = make_float4(0.f, 0.f, 0.f, 0.f);
        if (bvalid) bv = *(const float4*)(Bg + k0);
        As[lk + 0][lr] = av.x; As[lk + 1][lr] = av.y;
        As[lk + 2][lr] = av.z; As[lk + 3][lr] = av.w;
        Bs[lk + 0][lr] = bv.x; Bs[lk + 1][lr] = bv.y;
        Bs[lk + 2][lr] = bv.z; Bs[lk + 3][lr] = bv.w;
        __syncthreads();
#pragma unroll
        for (int k = 0; k < 8; k++) {
            float4 a0 = *(const float4*)&As[k][ty << 3];
            float4 a1 = *(const float4*)&As[k][(ty << 3) + 4];
            float4 b0 = *(const float4*)&Bs[k][tx << 3];
            float4 b1 = *(const float4*)&Bs[k][(tx << 3) + 4];
            float ar[8] = {a0.x, a0.y, a0.z, a0.w, a1.x, a1.y, a1.z, a1.w};
            float br[8] = {b0.x, b0.y, b0.z, b0.w, b1.x, b1.y, b1.z, b1.w};
#pragma unroll
            for (int i = 0; i < 8; i++)
#pragma unroll
                for (int j = 0; j < 8; j++)
                    acc[i][j] = fmaf(ar[i], br[j], acc[i][j]);
        }
        __syncthreads();
    }

#pragma unroll
    for (int i = 0; i < 8; i++) {
        int m = bm + (ty << 3) + i;
#pragma unroll
        for (int j = 0; j < 8; j++) {
            int n = bn + (tx << 3) + j;
            if (n < N) {
                float vv = acc[i][j];
                if (mode == 1) {
                    vv += bias[n];
                    vv = (vv > 15.f) ? vv : log1pf(__expf(vv));
                }
                C[(size_t)m * ldc + n] = vv;
            }
        }
    }
}

// ------ fused depthwise conv + SiLU + x_proj (8 rows per CTA) -----------------
__global__ void __launch_bounds__(256) k_convx(const float* __restrict__ cw,
                                               const float* __restrict__ cb,
                                               const float* __restrict__ Bw)
{
    int t0 = blockIdx.x * 8;
    __shared__ float xs[8][DI];
    int tid = threadIdx.x;
    for (int i = tid; i < 8 * DI; i += 256) {
        int r = i / DI, d = i - r * DI;
        int t = t0 + r;
        float s = cb[d];
        const float* w = cw + d * 4;
#pragma unroll
        for (int j = 0; j < 4; j++) {
            int tt = t - 3 + j;
            if (tt >= 0) s = fmaf(w[j], g_xz[tt * 2 * DI + d], s);
        }
        float v = s / (1.f + __expf(-s));
        xs[r][d] = v;
        g_xs[(size_t)t * DI + d] = v;
    }
    __syncthreads();

    int w = tid >> 5, lane = tid & 31;
    for (int n = w; n < 80; n += 8) {
        const float* bp = Bw + (size_t)n * DI;
        float acc[8];
#pragma unroll
        for (int r = 0; r < 8; r++) acc[r] = 0.f;
        for (int k = lane; k < DI; k += 32) {
            float wv = bp[k];
#pragma unroll
            for (int r = 0; r < 8; r++) acc[r] = fmaf(xs[r][k], wv, acc[r]);
        }
#pragma unroll
        for (int r = 0; r < 8; r++) {
#pragma unroll
            for (int o = 16; o; o >>= 1)
                acc[r] += __shfl_xor_sync(0xffffffffu, acc[r], o);
        }
        if (lane < 8) g_dbc[(size_t)(t0 + lane) * 80 + n] = acc[lane];
    }
}

// ---- selective scan: phase-structured (exp batch / recurrence / shfl batch) --
#define SU 8
__global__ void __launch_bounds__(256) k_scan(const float* __restrict__ Alog,
                                              const float* __restrict__ Dp)
{
    int tid = threadIdx.x;
    int grp = tid >> 4;
    int n = tid & 15;
    int d = blockIdx.x * 16 + grp;

    float A  = -__expf(Alog[d * DS + n]);
    float Dd = Dp[d];
    float h = 0.f;

    const float* dtp = g_dt + d;
    const float* xsp = g_xs + d;
    const float* zp  = g_xz + DI + d;
    const float* bp  = g_dbc + 48 + n;
    const float* cp  = g_dbc + 64 + n;

    float pd[SU], px[SU], pb[SU], pc[SU], pz[SU];
#pragma unroll
    for (int i = 0; i < SU; i++) {
        pd[i] = dtp[i * DI];
        px[i] = xsp[i * DI];
        pb[i] = bp[i * 80];
        pc[i] = cp[i * 80];
        pz[i] = zp[i * 2 * DI];
    }

    for (int t0 = 0; t0 < SEQ; t0 += SU) {
        float cd[SU], cx[SU], cb[SU], cc[SU], cz[SU];
#pragma unroll
        for (int i = 0; i < SU; i++) {
            cd[i] = pd[i]; cx[i] = px[i]; cb[i] = pb[i];
            cc[i] = pc[i]; cz[i] = pz[i];
        }
        int tn = t0 + SU;
        if (tn < SEQ) {
#pragma unroll
            for (int i = 0; i < SU; i++) {
                pd[i] = dtp[(tn + i) * DI];
                px[i] = xsp[(tn + i) * DI];
                pb[i] = bp[(tn + i) * 80];
                pc[i] = cp[(tn + i) * 80];
                pz[i] = zp[(tn + i) * 2 * DI];
            }
        }
        float ex[SU], db[SU];
#pragma unroll
        for (int i = 0; i < SU; i++) {
            ex[i] = __expf(cd[i] * A);
            db[i] = cd[i] * cb[i] * cx[i];
        }
        float hv[SU];
#pragma unroll
        for (int i = 0; i < SU; i++) {
            h = fmaf(ex[i], h, db[i]);
            hv[i] = h;
        }
        float yp[SU];
#pragma unroll
        for (int i = 0; i < SU; i++) yp[i] = hv[i] * cc[i];
#pragma unroll
        for (int o = 8; o; o >>= 1) {
#pragma unroll
            for (int i = 0; i < SU; i++)
                yp[i] += __shfl_xor_sync(0xffffffffu, yp[i], o);
        }
        if (n == 0) {
#pragma unroll
            for (int i = 0; i < SU; i++) {
                float z = cz[i];
                float y = fmaf(Dd, cx[i], yp[i]);
                float gv = y * (z / (1.f + __expf(-z)));
                __nv_bfloat16 hi = __float2bfloat16(gv);
                __nv_bfloat16 lo = __float2bfloat16(gv - __bfloat162float(hi));
                size_t base = (size_t)(t0 + i) * 4608 + d;
                g_a3[base]        = hi;
                g_a3[base + 1536] = lo;
                g_a3[base + 3072] = hi;
            }
        }
    }
}

// ---------------- host orchestration ------------------------------------------
extern "C" void kernel_launch(void* const* d_in, const int* in_sizes, int n_in,
                              void* d_out, int out_size)
{
    (void)in_sizes; (void)n_in; (void)out_size;
    const int*   ids   = (const int*)  d_in[0];
    const float* emb   = (const float*)d_in[1];
    const float* inw   = (const float*)d_in[2];
    const float* convw = (const float*)d_in[3];
    const float* convb = (const float*)d_in[4];
    const float* xpw   = (const float*)d_in[5];
    const float* dtw   = (const float*)d_in[6];
    const float* dtb   = (const float*)d_in[7];
    const float* alog  = (const float*)d_in[8];
    const float* Dp    = (const float*)d_in[9];
    const float* outw  = (const float*)d_in[10];
    const float* nw    = (const float*)d_in[11];
    const float* nfw   = (const float*)d_in[12];
    const float* lmw   = (const float*)d_in[13];
    float* out = (float*)d_out;

    static float *p_xzp = nullptr, *p_dbc = nullptr, *p_dt = nullptr, *p_xp = nullptr;
    static __nv_bfloat16 *p_a3 = nullptr, *p_win = nullptr, *p_wout = nullptr,
                         *p_lmbf = nullptr;
    if (!p_xzp) {
        cudaGetSymbolAddress((void**)&p_xzp,  g_xzp);
        cudaGetSymbolAddress((void**)&p_dbc,  g_dbc);
        cudaGetSymbolAddress((void**)&p_dt,   g_dt);
        cudaGetSymbolAddress((void**)&p_xp,   g_xp);
        cudaGetSymbolAddress((void**)&p_a3,   g_a3);
        cudaGetSymbolAddress((void**)&p_win,  g_win);
        cudaGetSymbolAddress((void**)&p_wout, g_wout);
        cudaGetSymbolAddress((void**)&p_lmbf, g_lmbf);
        cudaFuncSetAttribute(gemm_bf16,
                             cudaFuncAttributeMaxDynamicSharedMemorySize,
                             GEMM_SMEM);
    }

    const int EW = (SEQ * DM) / 256;

    // Launch order: index 3 = in_proj GEMM (ncu capture slot).
    k_init<<<EW, 256>>>(ids, emb);                               // 0
    {
        int tin = NLAYER * 3072 * DM;
        k_cvt3<<<(tin + 255) / 256, 256>>>(inw, p_win, DM, tin); // 1
    }

    for (int step = 0; step < 28; step++) {
        int li = (step < 22) ? step : 22 + ((step - 22) & 1);
        int flags = 0;
        if (step == 22) flags = F_SAVE;
        else if (step == 24 || step == 26) flags = F_ADD | F_SAVE;

        k_addnorm<<<SEQ, 256>>>(nw + (size_t)li * DM, flags);    // 2 (step 0)

        // in_proj split-K=3: g_xzp[z] = a3[:,z] @ win[:,z]^T  (1024 x 3072)
        gemm_bf16<<<dim3(24, 8, 3), 512, GEMM_SMEM>>>(           // 3 <- profiled
            p_a3, p_win + (size_t)li * 3072 * 2304, p_xzp,
            3072, 768, 2304, 2304, 3072, SEQ * 2 * DI);

        // sum partials -> g_xz
        k_sumxz<<<(SEQ * 2 * DI) / 256, 256>>>();

        // fused conv + silu + x_proj
        k_convx<<<SEQ / 8, 256>>>(convw + (size_t)li * DI * 4,
                                  convb + (size_t)li * DI,
                                  xpw + (size_t)li * 80 * DI);

        // dt = softplus(dbc[:, :48] @ dt_w^T + b)  (1024 x 1536, K=48)
        sgemm_nt<<<dim3(DI / 128, SEQ / 128), 256>>>(
            p_dbc, dtw + (size_t)li * DI * DTR, p_dt,
            DI, DTR, 80, DTR, DI, dtb + (size_t)li * DI, 1);

        // selective scan + gate -> A-triple g_a3 (1024 x 4608)
        k_scan<<<DI / 16, 256>>>(alog + (size_t)li * DI * DS,
                                 Dp + (size_t)li * DI);

        if (step == 0) {
            int tout = NLAYER * DM * DI;
            k_cvt3<<<(tout + 255) / 256, 256>>>(outw, p_wout, DI, tout);
        }

        // out_proj split-K=6: g_xp[z] = a3[:,z] @ wout[:,z]^T  (1024 x 768)
        gemm_bf16<<<dim3(6, 8, 6), 512, GEMM_SMEM>>>(
            p_a3, p_wout + (size_t)li * DM * 4608, p_xp,
            DM, 768, 4608, 4608, DM, SEQ * DM);
    }

    k_addnorm<<<SEQ, 256>>>(nfw, F_ADD);

    {
        int tlm = VOCAB * DM;
        k_cvt3<<<(tlm + 255) / 256, 256>>>(lmw, p_lmbf, DM, tlm);
    }
    // lm_head: out = a3 @ lmbf^T  (1024 x 50280, K'=2304)
    gemm_bf16<<<dim3((VOCAB + 127) / 128, 8, 1), 512, GEMM_SMEM>>>(
        p_a3, p_lmbf, out, VOCAB, 2304, 2304, 2304, VOCAB, 0);
}